// round 2
// baseline (speedup 1.0000x reference)
#include <cuda_runtime.h>
#include <math.h>

// Problem dims (fixed by the dataset)
#define NMAX   50000
#define EMAX   400000
#define E0MAX  200000
#define INCH   128
#define HID    32
#define FD     3
#define FDH    96      // FD*HID
#define OUTCH  32

// ---------------- scratch (static device globals; no allocation) ----------------
__device__ float  g_x   [NMAX * FDH];   // xc == x0 (always identical in reference)
__device__ float  g_y   [NMAX * FDH];
__device__ float  g_agg [NMAX * FDH];
__device__ float4 g_proj[NMAX];         // {sheaf_row, sheaf_col, wt_row, wt_col}
__device__ float4 g_t   [E0MAX];        // per-undirected-edge {t00, t01, w2, -}
__device__ float  g_deg [NMAX];
__device__ float  g_dinv[NMAX];
__device__ float  g_W1t [INCH * FDH];   // W1 transposed: [k][j]
__device__ float  g_W2t [FDH * OUTCH];  // W2 transposed: [k][o]
__device__ float  g_Wl  [9];            // spectral-normalized W_left (3x3 row-major [e][f])
__device__ float  g_WrT [HID * HID];    // spectral-normalized W_right transposed: [h][c]
__device__ float  g_coeff[FD];          // 1 + tanh(eps)

__device__ __forceinline__ float warp_sum(float v) {
    #pragma unroll
    for (int o = 16; o > 0; o >>= 1) v += __shfl_xor_sync(0xffffffffu, v, o);
    return v;
}

__device__ __forceinline__ float elu1(float t) {
    return t > 0.0f ? t : expm1f(t);
}

__device__ __forceinline__ void red_v4(float* p, float a, float b, float c, float d) {
    asm volatile("red.global.add.v4.f32 [%0], {%1,%2,%3,%4};"
                 :: "l"(p), "f"(a), "f"(b), "f"(c), "f"(d) : "memory");
}

// ---------------- prep: transpose W1, W2 ----------------
__global__ void k_prep(const float* __restrict__ W1, const float* __restrict__ W2) {
    int i = blockIdx.x * blockDim.x + threadIdx.x;
    if (i < INCH * FDH) {                       // W1 [96][128] -> W1t [128][96]
        int j = i / INCH, k = i % INCH;
        g_W1t[k * FDH + j] = W1[i];
    } else if (i < INCH * FDH + FDH * OUTCH) {  // W2 [32][96] -> W2t [96][32]
        int t = i - INCH * FDH;
        int o = t / FDH, k = t % FDH;
        g_W2t[k * OUTCH + o] = W2[t];
    }
}

// ---------------- K0: h = elu(x @ W1^T + b1) ----------------
// one warp per (node, 32-wide output group); 3 groups per node
__global__ void k_lin1(const float* __restrict__ x, const float* __restrict__ b1, int N) {
    int gw   = (blockIdx.x * blockDim.x + threadIdx.x) >> 5;
    int lane = threadIdx.x & 31;
    int n = gw / 3, jg = gw % 3;
    if (n >= N) return;
    int j = jg * 32 + lane;
    const float* xr = x + (size_t)n * INCH;
    float acc = b1[j];
    #pragma unroll 8
    for (int k = 0; k < INCH; k++)
        acc = fmaf(xr[k], g_W1t[k * FDH + j], acc);
    g_x[n * FDH + j] = elu1(acc);
}

// ---------------- spectral norm of W_left/W_right + coeff (one warp) ----------------
__global__ void k_spectral(const float* __restrict__ Wl_in,   // [9]
                           const float* __restrict__ Wr_in,   // [1024]
                           const float* __restrict__ eps_in)  // [3]
{
    __shared__ float W[HID * HID];
    __shared__ float u[HID], v[HID];
    int t = threadIdx.x;

    for (int i = t; i < HID * HID; i += 32) W[i] = Wr_in[i];
    u[t] = 0.1767766953f;  // 1/sqrt(32)
    __syncwarp();

    for (int it = 0; it < 20; it++) {
        float vj = 0.0f;
        #pragma unroll 8
        for (int i = 0; i < HID; i++) vj = fmaf(W[i * HID + t], u[i], vj);
        float nv = sqrtf(warp_sum(vj * vj)) + 1e-12f;
        v[t] = vj / nv;
        __syncwarp();
        float ui = 0.0f;
        #pragma unroll 8
        for (int j = 0; j < HID; j++) ui = fmaf(W[t * HID + j], v[j], ui);
        float nu = sqrtf(warp_sum(ui * ui)) + 1e-12f;
        u[t] = ui / nu;
        __syncwarp();
    }
    {   // v = normalize(W^T u)
        float vj = 0.0f;
        #pragma unroll 8
        for (int i = 0; i < HID; i++) vj = fmaf(W[i * HID + t], u[i], vj);
        float nv = sqrtf(warp_sum(vj * vj)) + 1e-12f;
        v[t] = vj / nv;
        __syncwarp();
    }
    // sigma = u^T W v
    float wi = 0.0f;
    #pragma unroll 8
    for (int j = 0; j < HID; j++) wi = fmaf(W[t * HID + j], v[j], wi);
    float sigma = warp_sum(u[t] * wi);
    float inv = 1.0f / sigma;
    for (int i = t; i < HID * HID; i += 32) {
        int c = i >> 5, h = i & 31;
        g_WrT[h * HID + c] = W[c * HID + h] * inv;  // store transposed
    }

    if (t == 0) {
        float Wl[9], ul[3], vl[3];
        #pragma unroll
        for (int i = 0; i < 9; i++) Wl[i] = Wl_in[i];
        ul[0] = ul[1] = ul[2] = 0.57735026919f;  // 1/sqrt(3)
        for (int it = 0; it < 20; it++) {
            #pragma unroll
            for (int j = 0; j < 3; j++)
                vl[j] = Wl[j] * ul[0] + Wl[3 + j] * ul[1] + Wl[6 + j] * ul[2];
            float nv = sqrtf(vl[0]*vl[0] + vl[1]*vl[1] + vl[2]*vl[2]) + 1e-12f;
            vl[0] /= nv; vl[1] /= nv; vl[2] /= nv;
            #pragma unroll
            for (int i = 0; i < 3; i++)
                ul[i] = Wl[i*3] * vl[0] + Wl[i*3+1] * vl[1] + Wl[i*3+2] * vl[2];
            float nu = sqrtf(ul[0]*ul[0] + ul[1]*ul[1] + ul[2]*ul[2]) + 1e-12f;
            ul[0] /= nu; ul[1] /= nu; ul[2] /= nu;
        }
        #pragma unroll
        for (int j = 0; j < 3; j++)
            vl[j] = Wl[j] * ul[0] + Wl[3 + j] * ul[1] + Wl[6 + j] * ul[2];
        float nv = sqrtf(vl[0]*vl[0] + vl[1]*vl[1] + vl[2]*vl[2]) + 1e-12f;
        vl[0] /= nv; vl[1] /= nv; vl[2] /= nv;
        float sig = 0.0f;
        #pragma unroll
        for (int i = 0; i < 3; i++)
            sig += ul[i] * (Wl[i*3] * vl[0] + Wl[i*3+1] * vl[1] + Wl[i*3+2] * vl[2]);
        float invl = 1.0f / sig;
        #pragma unroll
        for (int i = 0; i < 9; i++) g_Wl[i] = Wl[i] * invl;
        #pragma unroll
        for (int f = 0; f < 3; f++) g_coeff[f] = 1.0f + tanhf(eps_in[f]);
    }
}

// ---------------- K1: per-node projections for sheaf/weight learners ----------------
__global__ void k_proj(const float* __restrict__ ws, const float* __restrict__ wt, int N) {
    int n    = (blockIdx.x * blockDim.x + threadIdx.x) >> 5;
    int lane = threadIdx.x & 31;
    if (n >= N) return;
    const float* xr = g_x + n * FDH;
    float x0 = xr[lane], x1 = xr[32 + lane], x2 = xr[64 + lane];
    float sr = x0 * ws[lane]      + x1 * ws[32 + lane]  + x2 * ws[64 + lane];
    float sc = x0 * ws[96 + lane] + x1 * ws[128 + lane] + x2 * ws[160 + lane];
    float wr = x0 * wt[lane]      + x1 * wt[32 + lane]  + x2 * wt[64 + lane];
    float wc = x0 * wt[96 + lane] + x1 * wt[128 + lane] + x2 * wt[160 + lane];
    sr = warp_sum(sr); sc = warp_sum(sc); wr = warp_sum(wr); wc = warp_sum(wc);
    if (lane == 0) g_proj[n] = make_float4(sr, sc, wr, wc);
}

// ---------------- zero deg + agg ----------------
__global__ void k_zero(int N) {
    int total = N + N * FDH;
    for (int i = blockIdx.x * blockDim.x + threadIdx.x; i < total; i += gridDim.x * blockDim.x) {
        if (i < N) g_deg[i] = 0.0f;
        else       g_agg[i - N] = 0.0f;
    }
}

// ---------------- K2: per-undirected-edge transport + symmetric weight + degree ----------------
// Edge e and e+E0 are exact reverses: T_rev = T^T, same w2/cnorm.
__global__ void k_edgeU(const int* __restrict__ row, const int* __restrict__ col, int E0) {
    int e = blockIdx.x * blockDim.x + threadIdx.x;
    if (e >= E0) return;
    int r = row[e], c = col[e];
    float4 pr = g_proj[r], pc = g_proj[c];
    // forward edge: a = tanh(x_r . Ws_row + x_c . Ws_col); backward swaps endpoints
    float af = tanhf(pr.x + pc.y);
    float ab = tanhf(pc.x + pr.y);
    float af2 = af * af, ab2 = ab * ab;
    float invf = 1.0f / (1.0f + af2), invb = 1.0f / (1.0f + ab2);
    float cf = (1.0f - af2) * invf, sf = 2.0f * af * invf;
    float cb = (1.0f - ab2) * invb, sb = 2.0f * ab * invb;
    // T_fwd = Q_f^T Q_b = [[t00, t01], [-t01, t00]]
    float t00 = cf * cb + sf * sb;
    float t01 = sf * cb - cf * sb;
    float wf = 1.0f / (1.0f + expf(-(pr.z + pc.w)));
    float wb = 1.0f / (1.0f + expf(-(pc.z + pr.w)));
    float w = wf * wb, w2 = w * w;
    g_t[e] = make_float4(t00, t01, w2, 0.0f);
    atomicAdd(&g_deg[r], w2);
    atomicAdd(&g_deg[c], w2);
}

// ---------------- K3: dinv ----------------
__global__ void k_dinv(int N) {
    int n = blockIdx.x * blockDim.x + threadIdx.x;
    if (n >= N) return;
    float d = g_deg[n];
    g_dinv[n] = (d > 0.0f) ? rsqrtf(fmaxf(d, 1e-30f)) : 0.0f;
}

// ---------------- K4: y[n] = Wl * X_n * Wr^T ----------------
__global__ void k_y(int N) {
    __shared__ float sWrT[HID * HID];
    __shared__ float sWl[9];
    int tid = threadIdx.x;
    for (int i = tid; i < HID * HID; i += 128) sWrT[i] = g_WrT[i];
    if (tid < 9) sWl[tid] = g_Wl[tid];
    __syncthreads();

    int n = blockIdx.x * 4 + (tid >> 5);
    if (n >= N) return;
    int lane = tid & 31;
    const float* xr = g_x + n * FDH;
    float x0 = xr[lane], x1 = xr[32 + lane], x2 = xr[64 + lane];
    float m0 = sWl[0] * x0 + sWl[1] * x1 + sWl[2] * x2;
    float m1 = sWl[3] * x0 + sWl[4] * x1 + sWl[5] * x2;
    float m2 = sWl[6] * x0 + sWl[7] * x1 + sWl[8] * x2;
    float a0 = 0.0f, a1 = 0.0f, a2 = 0.0f;
    #pragma unroll 8
    for (int h = 0; h < HID; h++) {
        float b0 = __shfl_sync(0xffffffffu, m0, h);
        float b1 = __shfl_sync(0xffffffffu, m1, h);
        float b2 = __shfl_sync(0xffffffffu, m2, h);
        float wv = sWrT[h * HID + lane];
        a0 = fmaf(b0, wv, a0);
        a1 = fmaf(b1, wv, a1);
        a2 = fmaf(b2, wv, a2);
    }
    float* yo = g_y + n * FDH;
    yo[lane] = a0; yo[32 + lane] = a1; yo[64 + lane] = a2;
}

// ---------------- K5: edge aggregation (scatter, v4 reductions) ----------------
// one warp per DIRECTED edge; lanes 0..23 each handle 4 consecutive channels
__global__ void k_agg(const int* __restrict__ row, const int* __restrict__ col, int E, int E0) {
    int gw   = (blockIdx.x * blockDim.x + threadIdx.x) >> 5;
    int lane = threadIdx.x & 31;
    if (gw >= E) return;
    bool fwd = gw < E0;
    int eu = fwd ? gw : gw - E0;
    int a = row[eu], b = col[eu];
    int r = fwd ? a : b;
    int c = fwd ? b : a;
    float4 t = g_t[eu];
    float t00 = t.x;
    float t01 = fwd ? t.y : -t.y;
    float cn  = t.z * g_dinv[r] * g_dinv[c];
    if (lane >= 24) return;
    const float4* yv = (const float4*)(g_y + (size_t)c * FDH);
    float4 o;
    if (lane < 8) {              // f = 0: t00*y0 + t01*y1
        float4 y0 = yv[lane], y1 = yv[lane + 8];
        o.x = cn * fmaf(t00, y0.x, t01 * y1.x);
        o.y = cn * fmaf(t00, y0.y, t01 * y1.y);
        o.z = cn * fmaf(t00, y0.z, t01 * y1.z);
        o.w = cn * fmaf(t00, y0.w, t01 * y1.w);
    } else if (lane < 16) {      // f = 1: -t01*y0 + t00*y1
        float4 y0 = yv[lane - 8], y1 = yv[lane];
        o.x = cn * fmaf(t00, y1.x, -t01 * y0.x);
        o.y = cn * fmaf(t00, y1.y, -t01 * y0.y);
        o.z = cn * fmaf(t00, y1.z, -t01 * y0.z);
        o.w = cn * fmaf(t00, y1.w, -t01 * y0.w);
    } else {                     // f = 2: identity
        float4 y2 = yv[lane];
        o.x = cn * y2.x; o.y = cn * y2.y; o.z = cn * y2.z; o.w = cn * y2.w;
    }
    float* ao = g_agg + (size_t)r * FDH + lane * 4;
    red_v4(ao, o.x, o.y, o.z, o.w);
}

// ---------------- K6: z = elu(diag*y - agg); x = coeff*x - z ----------------
__global__ void k_update(int N) {
    int idx = blockIdx.x * blockDim.x + threadIdx.x;
    if (idx >= N * FDH) return;
    int n = idx / FDH;
    int f = (idx % FDH) >> 5;
    float diag = (g_deg[n] > 0.0f) ? 1.0f : 0.0f;
    float t = diag * g_y[idx] - g_agg[idx];
    float z = elu1(t);
    g_x[idx] = g_coeff[f] * g_x[idx] - z;
}

// ---------------- final: out = xc @ W2^T + b2 ----------------
__global__ void k_out(const float* __restrict__ b2, float* __restrict__ out, int N) {
    int n    = (blockIdx.x * blockDim.x + threadIdx.x) >> 5;
    int lane = threadIdx.x & 31;
    if (n >= N) return;
    const float* xr = g_x + n * FDH;
    float acc = b2[lane];
    #pragma unroll 8
    for (int k = 0; k < FDH; k++)
        acc = fmaf(xr[k], g_W2t[k * OUTCH + lane], acc);
    out[n * OUTCH + lane] = acc;
}

// ---------------- launch ----------------
extern "C" void kernel_launch(void* const* d_in, const int* in_sizes, int n_in,
                              void* d_out, int out_size)
{
    const float* x      = (const float*)d_in[0];
    const int*   ei     = (const int*)  d_in[1];
    const float* W1     = (const float*)d_in[2];
    const float* b1     = (const float*)d_in[3];
    const float* W2     = (const float*)d_in[4];
    const float* b2     = (const float*)d_in[5];
    const float* Wleft  = (const float*)d_in[6];   // [2,3,3]
    const float* Wright = (const float*)d_in[7];   // [2,32,32]
    const float* eps    = (const float*)d_in[8];   // [2,3,1]
    const float* Wsheaf = (const float*)d_in[9];   // [2,3,192]
    const float* Wwt    = (const float*)d_in[10];  // [2,1,192]
    float* out = (float*)d_out;

    int N  = in_sizes[0] / INCH;
    int E  = in_sizes[1] / 2;
    int E0 = E / 2;
    const int* row = ei;
    const int* col = ei + E;

    k_prep<<<(INCH * FDH + FDH * OUTCH + 255) / 256, 256>>>(W1, W2);
    k_lin1<<<(N * 3 * 32 + 255) / 256, 256>>>(x, b1, N);

    for (int layer = 0; layer < 2; layer++) {
        k_spectral<<<1, 32>>>(Wleft + layer * 9, Wright + layer * 1024, eps + layer * 3);
        k_proj<<<(N * 32 + 255) / 256, 256>>>(Wsheaf + layer * 576 + 192, Wwt + layer * 192, N);
        k_zero<<<2048, 256>>>(N);
        k_edgeU<<<(E0 + 255) / 256, 256>>>(row, col, E0);
        k_dinv<<<(N + 255) / 256, 256>>>(N);
        k_y<<<(N + 3) / 4, 128>>>(N);
        k_agg<<<(E * 32 + 255) / 256, 256>>>(row, col, E, E0);
        k_update<<<(N * FDH + 255) / 256, 256>>>(N);
    }

    k_out<<<(N * 32 + 255) / 256, 256>>>(b2, out, N);
}

// round 3
// speedup vs baseline: 1.4981x; 1.4981x over previous
#include <cuda_runtime.h>
#include <math.h>

// Problem dims (fixed by the dataset)
#define NMAX   50000
#define EMAX   400000
#define E0MAX  200000
#define INCH   128
#define HID    32
#define FD     3
#define FDH    96      // FD*HID
#define OUTCH  32

// ---------------- scratch (static device globals; no allocation) ----------------
__device__ float  g_x   [NMAX * FDH];   // xc == x0 (always identical in reference)
__device__ float  g_y   [NMAX * FDH];
__device__ float  g_agg [NMAX * FDH];
__device__ float4 g_proj[NMAX];         // {sheaf_row, sheaf_col, wt_row, wt_col}
__device__ float4 g_t   [E0MAX];        // per-undirected-edge {t00, t01, w2, -}
__device__ float  g_deg [NMAX];
__device__ float  g_W1t [INCH * FDH];   // W1 transposed: [k][j]
__device__ float  g_W2t [FDH * OUTCH];  // W2 transposed: [k][o]
__device__ float  g_Wl  [2 * 9];        // per-layer spectral-normalized W_left
__device__ float  g_WrT [2 * HID * HID];// per-layer normalized W_right, transposed [h][c]
__device__ float  g_coeff[2 * FD];      // per-layer 1 + tanh(eps)

__device__ __forceinline__ float warp_sum(float v) {
    #pragma unroll
    for (int o = 16; o > 0; o >>= 1) v += __shfl_xor_sync(0xffffffffu, v, o);
    return v;
}

__device__ __forceinline__ float elu1(float t) {
    return t > 0.0f ? t : expm1f(t);
}

__device__ __forceinline__ void red_v4(float* p, float a, float b, float c, float d) {
    asm volatile("red.global.add.v4.f32 [%0], {%1,%2,%3,%4};"
                 :: "l"(p), "f"(a), "f"(b), "f"(c), "f"(d) : "memory");
}

// ---------------- prep: transpose W1, W2 ----------------
__global__ void k_prep(const float* __restrict__ W1, const float* __restrict__ W2) {
    int i = blockIdx.x * blockDim.x + threadIdx.x;
    if (i < INCH * FDH) {                       // W1 [96][128] -> W1t [128][96]
        int j = i / INCH, k = i % INCH;
        g_W1t[k * FDH + j] = W1[i];
    } else if (i < INCH * FDH + FDH * OUTCH) {  // W2 [32][96] -> W2t [96][32]
        int t = i - INCH * FDH;
        int o = t / FDH, k = t % FDH;
        g_W2t[k * OUTCH + o] = W2[t];
    }
}

// ---------------- spectral norm of W_left/W_right + coeff; one block per layer ----------------
__global__ void k_spectral(const float* __restrict__ Wl_in,   // [2,9]
                           const float* __restrict__ Wr_in,   // [2,1024]
                           const float* __restrict__ eps_in)  // [2,3]
{
    int layer = blockIdx.x;
    const float* wl = Wl_in + layer * 9;
    const float* wr = Wr_in + layer * HID * HID;
    const float* ep = eps_in + layer * 3;

    __shared__ float W[HID * HID];
    __shared__ float u[HID], v[HID];
    int t = threadIdx.x;

    for (int i = t; i < HID * HID; i += 32) W[i] = wr[i];
    u[t] = 0.1767766953f;  // 1/sqrt(32)
    __syncwarp();

    for (int it = 0; it < 20; it++) {
        float vj = 0.0f;
        #pragma unroll 8
        for (int i = 0; i < HID; i++) vj = fmaf(W[i * HID + t], u[i], vj);
        float nv = sqrtf(warp_sum(vj * vj)) + 1e-12f;
        v[t] = vj / nv;
        __syncwarp();
        float ui = 0.0f;
        #pragma unroll 8
        for (int j = 0; j < HID; j++) ui = fmaf(W[t * HID + j], v[j], ui);
        float nu = sqrtf(warp_sum(ui * ui)) + 1e-12f;
        u[t] = ui / nu;
        __syncwarp();
    }
    {   // v = normalize(W^T u)
        float vj = 0.0f;
        #pragma unroll 8
        for (int i = 0; i < HID; i++) vj = fmaf(W[i * HID + t], u[i], vj);
        float nv = sqrtf(warp_sum(vj * vj)) + 1e-12f;
        v[t] = vj / nv;
        __syncwarp();
    }
    // sigma = u^T W v
    float wi = 0.0f;
    #pragma unroll 8
    for (int j = 0; j < HID; j++) wi = fmaf(W[t * HID + j], v[j], wi);
    float sigma = warp_sum(u[t] * wi);
    float inv = 1.0f / sigma;
    for (int i = t; i < HID * HID; i += 32) {
        int c = i >> 5, h = i & 31;
        g_WrT[layer * HID * HID + h * HID + c] = W[c * HID + h] * inv;  // transposed
    }

    if (t == 0) {
        float Wl[9], ul[3], vl[3];
        #pragma unroll
        for (int i = 0; i < 9; i++) Wl[i] = wl[i];
        ul[0] = ul[1] = ul[2] = 0.57735026919f;  // 1/sqrt(3)
        for (int it = 0; it < 20; it++) {
            #pragma unroll
            for (int j = 0; j < 3; j++)
                vl[j] = Wl[j] * ul[0] + Wl[3 + j] * ul[1] + Wl[6 + j] * ul[2];
            float nv = sqrtf(vl[0]*vl[0] + vl[1]*vl[1] + vl[2]*vl[2]) + 1e-12f;
            vl[0] /= nv; vl[1] /= nv; vl[2] /= nv;
            #pragma unroll
            for (int i = 0; i < 3; i++)
                ul[i] = Wl[i*3] * vl[0] + Wl[i*3+1] * vl[1] + Wl[i*3+2] * vl[2];
            float nu = sqrtf(ul[0]*ul[0] + ul[1]*ul[1] + ul[2]*ul[2]) + 1e-12f;
            ul[0] /= nu; ul[1] /= nu; ul[2] /= nu;
        }
        #pragma unroll
        for (int j = 0; j < 3; j++)
            vl[j] = Wl[j] * ul[0] + Wl[3 + j] * ul[1] + Wl[6 + j] * ul[2];
        float nv = sqrtf(vl[0]*vl[0] + vl[1]*vl[1] + vl[2]*vl[2]) + 1e-12f;
        vl[0] /= nv; vl[1] /= nv; vl[2] /= nv;
        float sig = 0.0f;
        #pragma unroll
        for (int i = 0; i < 3; i++)
            sig += ul[i] * (Wl[i*3] * vl[0] + Wl[i*3+1] * vl[1] + Wl[i*3+2] * vl[2]);
        float invl = 1.0f / sig;
        #pragma unroll
        for (int i = 0; i < 9; i++) g_Wl[layer * 9 + i] = Wl[i] * invl;
        #pragma unroll
        for (int f = 0; f < 3; f++) g_coeff[layer * 3 + f] = 1.0f + tanhf(ep[f]);
    }
}

// ---------------- proj helper: lane holds channels (lane, 32+lane, 64+lane) ----------------
__device__ __forceinline__ void do_proj(int n, int lane, float h0, float h1, float h2,
                                        const float* __restrict__ ws,
                                        const float* __restrict__ wt) {
    float sr = h0 * ws[lane]      + h1 * ws[32 + lane]  + h2 * ws[64 + lane];
    float sc = h0 * ws[96 + lane] + h1 * ws[128 + lane] + h2 * ws[160 + lane];
    float wr = h0 * wt[lane]      + h1 * wt[32 + lane]  + h2 * wt[64 + lane];
    float wc = h0 * wt[96 + lane] + h1 * wt[128 + lane] + h2 * wt[160 + lane];
    sr = warp_sum(sr); sc = warp_sum(sc); wr = warp_sum(wr); wc = warp_sum(wc);
    if (lane == 0) {
        g_proj[n] = make_float4(sr, sc, wr, wc);
        g_deg[n] = 0.0f;
    }
}

// ---------------- K0: x = elu(in @ W1^T + b1); + layer-0 projections; + deg=0 ----------------
// one warp per node; lane owns output channels {lane, 32+lane, 64+lane}
__global__ void __launch_bounds__(256) k_lin1(const float* __restrict__ x,
                                              const float* __restrict__ b1,
                                              const float* __restrict__ ws,
                                              const float* __restrict__ wt, int N) {
    int n    = (blockIdx.x * blockDim.x + threadIdx.x) >> 5;
    int lane = threadIdx.x & 31;
    if (n >= N) return;
    const float* xr = x + (size_t)n * INCH;
    float xv[4];
    #pragma unroll
    for (int q = 0; q < 4; q++) xv[q] = xr[q * 32 + lane];
    float a0 = b1[lane], a1 = b1[32 + lane], a2 = b1[64 + lane];
    #pragma unroll 4
    for (int k = 0; k < INCH; k++) {
        float xk = __shfl_sync(0xffffffffu, xv[k >> 5], k & 31);
        a0 = fmaf(xk, g_W1t[k * FDH + lane],      a0);
        a1 = fmaf(xk, g_W1t[k * FDH + 32 + lane], a1);
        a2 = fmaf(xk, g_W1t[k * FDH + 64 + lane], a2);
    }
    a0 = elu1(a0); a1 = elu1(a1); a2 = elu1(a2);
    float* xo = g_x + n * FDH;
    xo[lane] = a0; xo[32 + lane] = a1; xo[64 + lane] = a2;
    do_proj(n, lane, a0, a1, a2, ws, wt);
}

// ---------------- K2: per-undirected-edge transport + symmetric weight + degree ----------------
__global__ void __launch_bounds__(256) k_edgeU(const int* __restrict__ row,
                                               const int* __restrict__ col, int E0) {
    int e = blockIdx.x * blockDim.x + threadIdx.x;
    if (e >= E0) return;
    int r = row[e], c = col[e];
    float4 pr = g_proj[r], pc = g_proj[c];
    float af = tanhf(pr.x + pc.y);
    float ab = tanhf(pc.x + pr.y);
    float af2 = af * af, ab2 = ab * ab;
    float invf = 1.0f / (1.0f + af2), invb = 1.0f / (1.0f + ab2);
    float cf = (1.0f - af2) * invf, sf = 2.0f * af * invf;
    float cb = (1.0f - ab2) * invb, sb = 2.0f * ab * invb;
    float t00 = cf * cb + sf * sb;
    float t01 = sf * cb - cf * sb;
    float wf = 1.0f / (1.0f + expf(-(pr.z + pc.w)));
    float wb = 1.0f / (1.0f + expf(-(pc.z + pr.w)));
    float w = wf * wb, w2 = w * w;
    g_t[e] = make_float4(t00, t01, w2, 0.0f);
    atomicAdd(&g_deg[r], w2);
    atomicAdd(&g_deg[c], w2);
}

// ---------------- K4: y[n] = Wl * X_n * Wr^T ; zero agg[n] ----------------
__global__ void __launch_bounds__(128) k_y(int layer, int N) {
    __shared__ float sWrT[HID * HID];
    __shared__ float sWl[9];
    int tid = threadIdx.x;
    for (int i = tid; i < HID * HID; i += 128) sWrT[i] = g_WrT[layer * HID * HID + i];
    if (tid < 9) sWl[tid] = g_Wl[layer * 9 + tid];
    __syncthreads();

    int n = blockIdx.x * 4 + (tid >> 5);
    if (n >= N) return;
    int lane = tid & 31;
    const float* xr = g_x + n * FDH;
    float x0 = xr[lane], x1 = xr[32 + lane], x2 = xr[64 + lane];
    float m0 = sWl[0] * x0 + sWl[1] * x1 + sWl[2] * x2;
    float m1 = sWl[3] * x0 + sWl[4] * x1 + sWl[5] * x2;
    float m2 = sWl[6] * x0 + sWl[7] * x1 + sWl[8] * x2;
    float a0 = 0.0f, a1 = 0.0f, a2 = 0.0f;
    #pragma unroll 8
    for (int h = 0; h < HID; h++) {
        float b0 = __shfl_sync(0xffffffffu, m0, h);
        float b1 = __shfl_sync(0xffffffffu, m1, h);
        float b2 = __shfl_sync(0xffffffffu, m2, h);
        float wv = sWrT[h * HID + lane];
        a0 = fmaf(b0, wv, a0);
        a1 = fmaf(b1, wv, a1);
        a2 = fmaf(b2, wv, a2);
    }
    float* yo = g_y + n * FDH;
    float* ag = g_agg + n * FDH;
    yo[lane] = a0; yo[32 + lane] = a1; yo[64 + lane] = a2;
    ag[lane] = 0.0f; ag[32 + lane] = 0.0f; ag[64 + lane] = 0.0f;
}

// ---------------- K5: edge aggregation — 8 threads per directed edge ----------------
__global__ void __launch_bounds__(256) k_agg(const int* __restrict__ row,
                                             const int* __restrict__ col, int E, int E0) {
    int gt  = blockIdx.x * blockDim.x + threadIdx.x;
    int e   = gt >> 3;
    int sub = gt & 7;
    if (e >= E) return;
    bool fwd = e < E0;
    int eu = fwd ? e : e - E0;
    int a = row[eu], b = col[eu];
    int r = fwd ? a : b;
    int c = fwd ? b : a;
    float4 t = g_t[eu];
    float t00 = t.x;
    float t01 = fwd ? t.y : -t.y;
    float dr = g_deg[r], dc = g_deg[c];
    float ir = (dr > 0.0f) ? rsqrtf(fmaxf(dr, 1e-30f)) : 0.0f;
    float ic = (dc > 0.0f) ? rsqrtf(fmaxf(dc, 1e-30f)) : 0.0f;
    float cn = t.z * ir * ic;
    const float4* yv = (const float4*)(g_y + (size_t)c * FDH);
    float4 y0 = yv[sub], y1 = yv[8 + sub], y2 = yv[16 + sub];
    float* ao = g_agg + (size_t)r * FDH + sub * 4;
    red_v4(ao,
           cn * fmaf(t00, y0.x,  t01 * y1.x),
           cn * fmaf(t00, y0.y,  t01 * y1.y),
           cn * fmaf(t00, y0.z,  t01 * y1.z),
           cn * fmaf(t00, y0.w,  t01 * y1.w));
    red_v4(ao + 32,
           cn * fmaf(t00, y1.x, -t01 * y0.x),
           cn * fmaf(t00, y1.y, -t01 * y0.y),
           cn * fmaf(t00, y1.z, -t01 * y0.z),
           cn * fmaf(t00, y1.w, -t01 * y0.w));
    red_v4(ao + 64, cn * y2.x, cn * y2.y, cn * y2.z, cn * y2.w);
}

// ---------------- K6a: layer-0 update; + layer-1 projections; + deg=0 ----------------
__global__ void __launch_bounds__(256) k_upd_proj(const float* __restrict__ ws,
                                                  const float* __restrict__ wt, int N) {
    int n    = (blockIdx.x * blockDim.x + threadIdx.x) >> 5;
    int lane = threadIdx.x & 31;
    if (n >= N) return;
    float diag = (g_deg[n] > 0.0f) ? 1.0f : 0.0f;
    const float* yr = g_y   + n * FDH;
    const float* ar = g_agg + n * FDH;
    float* xr = g_x + n * FDH;
    float c0 = g_coeff[0], c1 = g_coeff[1], c2 = g_coeff[2];
    float x0 = c0 * xr[lane]      - elu1(diag * yr[lane]      - ar[lane]);
    float x1 = c1 * xr[32 + lane] - elu1(diag * yr[32 + lane] - ar[32 + lane]);
    float x2 = c2 * xr[64 + lane] - elu1(diag * yr[64 + lane] - ar[64 + lane]);
    xr[lane] = x0; xr[32 + lane] = x1; xr[64 + lane] = x2;
    do_proj(n, lane, x0, x1, x2, ws, wt);
}

// ---------------- K6b: layer-1 update fused with final GEMM ----------------
__global__ void __launch_bounds__(256) k_upd_out(const float* __restrict__ b2,
                                                 float* __restrict__ out, int N) {
    int n    = (blockIdx.x * blockDim.x + threadIdx.x) >> 5;
    int lane = threadIdx.x & 31;
    if (n >= N) return;
    float diag = (g_deg[n] > 0.0f) ? 1.0f : 0.0f;
    const float* yr = g_y   + n * FDH;
    const float* ar = g_agg + n * FDH;
    float* xr = g_x + n * FDH;
    float c0 = g_coeff[3], c1 = g_coeff[4], c2 = g_coeff[5];
    float x0 = c0 * xr[lane]      - elu1(diag * yr[lane]      - ar[lane]);
    float x1 = c1 * xr[32 + lane] - elu1(diag * yr[32 + lane] - ar[32 + lane]);
    float x2 = c2 * xr[64 + lane] - elu1(diag * yr[64 + lane] - ar[64 + lane]);
    float acc = b2[lane];
    #pragma unroll 8
    for (int k = 0; k < 32; k++) {
        float xk = __shfl_sync(0xffffffffu, x0, k);
        acc = fmaf(xk, g_W2t[k * OUTCH + lane], acc);
    }
    #pragma unroll 8
    for (int k = 0; k < 32; k++) {
        float xk = __shfl_sync(0xffffffffu, x1, k);
        acc = fmaf(xk, g_W2t[(32 + k) * OUTCH + lane], acc);
    }
    #pragma unroll 8
    for (int k = 0; k < 32; k++) {
        float xk = __shfl_sync(0xffffffffu, x2, k);
        acc = fmaf(xk, g_W2t[(64 + k) * OUTCH + lane], acc);
    }
    out[n * OUTCH + lane] = acc;
}

// ---------------- launch ----------------
extern "C" void kernel_launch(void* const* d_in, const int* in_sizes, int n_in,
                              void* d_out, int out_size)
{
    const float* x      = (const float*)d_in[0];
    const int*   ei     = (const int*)  d_in[1];
    const float* W1     = (const float*)d_in[2];
    const float* b1     = (const float*)d_in[3];
    const float* W2     = (const float*)d_in[4];
    const float* b2     = (const float*)d_in[5];
    const float* Wleft  = (const float*)d_in[6];   // [2,3,3]
    const float* Wright = (const float*)d_in[7];   // [2,32,32]
    const float* eps    = (const float*)d_in[8];   // [2,3,1]
    const float* Wsheaf = (const float*)d_in[9];   // [2,3,192]
    const float* Wwt    = (const float*)d_in[10];  // [2,1,192]
    float* out = (float*)d_out;

    int N  = in_sizes[0] / INCH;
    int E  = in_sizes[1] / 2;
    int E0 = E / 2;
    const int* row = ei;
    const int* col = ei + E;

    k_prep<<<(INCH * FDH + FDH * OUTCH + 255) / 256, 256>>>(W1, W2);
    k_spectral<<<2, 32>>>(Wleft, Wright, eps);
    k_lin1<<<(N * 32 + 255) / 256, 256>>>(x, b1, Wsheaf + 192, Wwt, N);

    for (int layer = 0; layer < 2; layer++) {
        k_edgeU<<<(E0 + 255) / 256, 256>>>(row, col, E0);
        k_y<<<(N + 3) / 4, 128>>>(layer, N);
        k_agg<<<(E * 8 + 255) / 256, 256>>>(row, col, E, E0);
        if (layer == 0)
            k_upd_proj<<<(N * 32 + 255) / 256, 256>>>(Wsheaf + 576 + 192, Wwt + 192, N);
        else
            k_upd_out<<<(N * 32 + 255) / 256, 256>>>(b2, out, N);
    }
}